// round 15
// baseline (speedup 1.0000x reference)
#include <cuda_runtime.h>
#include <cuda_fp16.h>
#include <cstdint>

// Problem constants
#define NB 2
#define NL 2048
#define NDM 1024
#define NH 16
#define ND 64
#define NM (NB*NL)   // 4096

// Scratch — projection outputs ROW-MAJOR [m][NDM] (m = b*NL + l, col = h*64 + d)
__device__ __half g_x16[(size_t)NM*NDM];            // x rounded to fp16
__device__ __half g_w16[5][(size_t)NDM*NDM];        // weights fp16, ORIGINAL [k][n] layout
__device__ __half g_q16 [(size_t)NM*NDM];           // q
__device__ __half g_k16 [(size_t)NM*NDM];           // k
__device__ __half g_kr16[(size_t)NM*NDM];           // kr (natural; flash uses ldmatrix.trans)
__device__ float  g_qr32[(size_t)NM*NDM];           // qr fp32
__device__ __half g_att16[(size_t)NM*NDM];          // attention output fp16

// ---------------------------------------------------------------------------
__device__ __forceinline__ uint32_t smem_u32(const void* p) {
    uint32_t a;
    asm("{ .reg .u64 t; cvta.to.shared.u64 t, %1; cvt.u32.u64 %0, t; }" : "=r"(a) : "l"(p));
    return a;
}
#define MMA_F16(d0,d1,d2,d3,a0,a1,a2,a3,b0,b1) \
    asm volatile("mma.sync.aligned.m16n8k16.row.col.f32.f16.f16.f32 " \
        "{%0,%1,%2,%3},{%4,%5,%6,%7},{%8,%9},{%0,%1,%2,%3};" \
        : "+f"(d0), "+f"(d1), "+f"(d2), "+f"(d3) \
        : "r"(a0), "r"(a1), "r"(a2), "r"(a3), "r"(b0), "r"(b1))
#define LDSM_X4(r0,r1,r2,r3,addr) \
    asm volatile("ldmatrix.sync.aligned.m8n8.x4.shared.b16 {%0,%1,%2,%3}, [%4];" \
        : "=r"(r0), "=r"(r1), "=r"(r2), "=r"(r3) : "r"(addr))
#define LDSM_X4_T(r0,r1,r2,r3,addr) \
    asm volatile("ldmatrix.sync.aligned.m8n8.x4.trans.shared.b16 {%0,%1,%2,%3}, [%4];" \
        : "=r"(r0), "=r"(r1), "=r"(r2), "=r"(r3) : "r"(addr))
// exp2 of two fp32 args -> packed fp16x2
__device__ __forceinline__ uint32_t ex2h2(float a0, float a1) {
    uint32_t r;
    asm("{ .reg .b32 t; cvt.rn.f16x2.f32 t, %2, %1; ex2.approx.f16x2 %0, t; }"
        : "=r"(r) : "f"(a0), "f"(a1));
    return r;
}

// ---------------------------------------------------------------------------
// Pre-passes: elementwise fp16 conversion (no transpose anywhere)
// ---------------------------------------------------------------------------
__global__ __launch_bounds__(256) void cvt_x(const float4* __restrict__ x) {
    int i = blockIdx.x * 256 + threadIdx.x;
    float4 v = x[i];
    ((__half2*)g_x16)[2*i+0] = __floats2half2_rn(v.x, v.y);
    ((__half2*)g_x16)[2*i+1] = __floats2half2_rn(v.z, v.w);
}
__global__ __launch_bounds__(256) void wcvt(
    const float4* __restrict__ w0, const float4* __restrict__ w1,
    const float4* __restrict__ w2, const float4* __restrict__ w3,
    const float4* __restrict__ w4)
{
    int mat = blockIdx.y;
    const float4* W = (mat==0)?w0:(mat==1)?w1:(mat==2)?w2:(mat==3)?w3:w4;
    int i = blockIdx.x * 256 + threadIdx.x;      // 262144 float4 per matrix
    float4 v = W[i];
    ((__half2*)g_w16[mat])[2*i+0] = __floats2half2_rn(v.x, v.y);
    ((__half2*)g_w16[mat])[2*i+1] = __floats2half2_rn(v.z, v.w);
}

// ---------------------------------------------------------------------------
// fp16 GEMM (m16n8k16), 256x128x64 CTA tile, 256 thr / 8 warps (64x64 each,
// warp grid 4m x 2n), 3-stage cp.async. A [m][k] str 72h; B = W [k][n] str
// 136h, frags via ldmatrix.trans. 1 CTA/SM (162.8 KB smem). Row-major epilogue.
// mode 0: A=g_x16, W=g_w16[z] -> q/k/qr/kr. mode 1: att @ wo -> Cout.
// ---------------------------------------------------------------------------
#define BM 256
#define BN 128
#define BK 64
#define ASTRH 72                       // A row stride (halves)
#define BSTRH 136                      // B row stride (halves): trans-LDSM conflict-free
#define AHALFS (BM*ASTRH)              // 18432
#define ABYTES (AHALFS*2)              // 36864
#define BHALFS (BK*BSTRH)              // 8704
#define STG_HALFS (AHALFS + BHALFS)    // 27136 halves = 54272 B per stage
#define NITER (NDM/BK)                 // 16

__device__ __forceinline__ void load_stage(
    const __half* __restrict__ A, const __half* __restrict__ W,
    int m0, int n0, int k0, uint32_t sA, uint32_t sB, int t)
{
#pragma unroll
    for (int i = 0; i < 8; i++) {      // A tile 256x64 halves: 2048 chunks
        int idx = t + i*256;
        int row = idx >> 3, seg = idx & 7;
        asm volatile("cp.async.cg.shared.global [%0], [%1], 16;"
                     :: "r"(sA + (uint32_t)((row*ASTRH + seg*8)*2)),
                        "l"(A + (size_t)(m0 + row)*NDM + k0 + seg*8));
    }
#pragma unroll
    for (int i = 0; i < 4; i++) {      // B tile 64(k)x128(n) halves: 1024 chunks
        int idx = t + i*256;
        int row = idx >> 4, seg = idx & 15;
        asm volatile("cp.async.cg.shared.global [%0], [%1], 16;"
                     :: "r"(sB + (uint32_t)((row*BSTRH + seg*8)*2)),
                        "l"(W + (size_t)(k0 + row)*NDM + n0 + seg*8));
    }
}

__global__ __launch_bounds__(256, 1) void gemm_tc(float* __restrict__ Cout, int mode)
{
    extern __shared__ __half sm[];
    const uint32_t smb = smem_u32(sm);

    const int t = threadIdx.x;
    const int wid = t >> 5, lane = t & 31;
    const int gid = lane >> 2, tg = lane & 3;
    const int g8 = lane >> 3, lr = lane & 7;
    const int warp_m = (wid >> 1) * 64;   // 0,64,128,192
    const int warp_n = (wid & 1) * 64;    // 0,64

    const int mat = (mode == 0) ? (int)blockIdx.z : 4;
    const __half* A = (mode == 0) ? g_x16 : g_att16;
    const __half* W = g_w16[mat];
    const int m0 = blockIdx.y * BM, n0 = blockIdx.x * BN;

    uint32_t aoff[4], boffT[4];
#pragma unroll
    for (int mt = 0; mt < 4; mt++)
        aoff[mt] = (uint32_t)(((warp_m + mt*16 + (g8&1)*8 + lr)*ASTRH + (g8>>1)*8) * 2);
#pragma unroll
    for (int i = 0; i < 4; i++)   // trans pattern: row = k, col = n
        boffT[i] = (uint32_t)ABYTES +
                   (uint32_t)((((g8&1)*8 + lr)*BSTRH + warp_n + i*16 + (g8>>1)*8) * 2);

    float acc[4][8][4];
#pragma unroll
    for (int mt = 0; mt < 4; mt++)
#pragma unroll
        for (int nt = 0; nt < 8; nt++)
#pragma unroll
            for (int c = 0; c < 4; c++) acc[mt][nt][c] = 0.f;

#pragma unroll
    for (int p = 0; p < 2; p++) {
        uint32_t base = smb + (uint32_t)(p * STG_HALFS) * 2u;
        load_stage(A, W, m0, n0, p * BK, base, base + ABYTES, t);
        asm volatile("cp.async.commit_group;" ::: "memory");
    }
    asm volatile("cp.async.wait_group 1;" ::: "memory");
    __syncthreads();

    for (int i = 0; i < NITER; i++) {
        const int s = i % 3;
        if (i + 2 < NITER) {
            uint32_t base = smb + (uint32_t)(((i+2)%3) * STG_HALFS) * 2u;
            load_stage(A, W, m0, n0, (i+2)*BK, base, base + ABYTES, t);
        }
        asm volatile("cp.async.commit_group;" ::: "memory");

        const uint32_t stb = smb + (uint32_t)(s * STG_HALFS) * 2u;
#pragma unroll
        for (int kk = 0; kk < 4; kk++) {
            const uint32_t kbA = (uint32_t)kk * 32u;                 // 16 halves along k
            const uint32_t kbB = (uint32_t)(kk * 16 * BSTRH * 2);    // 16 k-rows
            uint32_t a[4][4], b[8][2];
#pragma unroll
            for (int mt = 0; mt < 4; mt++)
                LDSM_X4(a[mt][0], a[mt][1], a[mt][2], a[mt][3], stb + aoff[mt] + kbA);
#pragma unroll
            for (int i4 = 0; i4 < 4; i4++)
                LDSM_X4_T(b[2*i4][0], b[2*i4][1], b[2*i4+1][0], b[2*i4+1][1],
                          stb + boffT[i4] + kbB);
#pragma unroll
            for (int mt = 0; mt < 4; mt++)
#pragma unroll
                for (int nt = 0; nt < 8; nt++)
                    MMA_F16(acc[mt][nt][0], acc[mt][nt][1], acc[mt][nt][2], acc[mt][nt][3],
                            a[mt][0], a[mt][1], a[mt][2], a[mt][3],
                            b[nt][0], b[nt][1]);
        }

        asm volatile("cp.async.wait_group 1;" ::: "memory");
        __syncthreads();
    }

    // Row-major epilogue for everything
#pragma unroll
    for (int mt = 0; mt < 4; mt++) {
#pragma unroll
        for (int nt = 0; nt < 8; nt++) {
            float v0 = acc[mt][nt][0], v1 = acc[mt][nt][1];
            float v2 = acc[mt][nt][2], v3 = acc[mt][nt][3];
            int col = n0 + warp_n + nt*8 + 2*tg;
            size_t r0 = (size_t)(m0 + warp_m + mt*16 + gid), r1 = r0 + 8;
            if (mode == 1) {
                *(float2*)(Cout + r0*NDM + col) = make_float2(v0, v1);
                *(float2*)(Cout + r1*NDM + col) = make_float2(v2, v3);
            } else if (mat == 2) {
                *(float2*)(g_qr32 + r0*NDM + col) = make_float2(v0, v1);
                *(float2*)(g_qr32 + r1*NDM + col) = make_float2(v2, v3);
            } else {
                __half* base = (mat == 0) ? g_q16 : (mat == 1) ? g_k16 : g_kr16;
                *(__half2*)(base + r0*NDM + col) = __floats2half2_rn(v0, v1);
                *(__half2*)(base + r1*NDM + col) = __floats2half2_rn(v2, v3);
            }
        }
    }
}

// ---------------------------------------------------------------------------
// Flash attention, fp16 mma, no online max. 64-query tile, 128 thr / 4 warps.
// 128-key double-buffered stages; intra-tile software pipelining:
//   S0 -> P0=ex2(S0) -> S1-mma (covers ex2 latency) -> O+=P0@Kr0 -> P1 -> O+=P1@Kr1
// Kr natural [key][d]; O-mma B frags via ldmatrix.trans.
// smem = 4 x (128*72) fp16 = 73728 B -> 3 CTAs/SM.
// ---------------------------------------------------------------------------
#define FSTRH 72
#define KT_HALFS (128*FSTRH)         // 9216 per stage
#define KT_BYTES (KT_HALFS*2)        // 18432
#define HALF_BYTES (64*FSTRH*2)      // 9216 B (64 key rows)
#define ONES_H2 0x3C003C00u

__global__ __launch_bounds__(128, 3) void flash_mma()
{
    extern __shared__ __half fh[];
    __half* sKt = fh;                          // 2 x [128][72] K natural; Q staged in stage 0
    __half* sKr = fh + 2*KT_HALFS;             // 2 x [128][72] Kr natural [key][d]
    const uint32_t sKtb = smem_u32(sKt);
    const uint32_t sKrb = smem_u32(sKr);

    const int qt = (int)(gridDim.x - 1 - blockIdx.x);   // heavy tiles first
    const int bh = blockIdx.y;
    const int bb = bh >> 4, hh = bh & 15;
    const __half* qp  = g_q16  + (size_t)(bb*NL)*NDM + hh*64;
    const __half* kp  = g_k16  + (size_t)(bb*NL)*NDM + hh*64;
    const __half* krp = g_kr16 + (size_t)(bb*NL)*NDM + hh*64;
    const float*  qrp = g_qr32 + (size_t)(bb*NL)*NDM + hh*64;

    const int t = threadIdx.x;
    const int wid = t >> 5, lane = t & 31;
    const int gid = lane >> 2, tg = lane & 3;
    const int g8 = lane >> 3, lr = lane & 7;
    const int wm = wid * 16;

    uint32_t foff[4], foffT[4];
#pragma unroll
    for (int i = 0; i < 4; i++) {
        foff[i]  = (uint32_t)(((i*16 + (g8>>1)*8 + lr)*FSTRH + (g8&1)*8) * 2);
        foffT[i] = (uint32_t)(((((g8&1)*8) + lr)*FSTRH + i*16 + (g8>>1)*8) * 2);
    }
    const uint32_t qoff =
        (uint32_t)(((wm + (g8&1)*8 + lr)*FSTRH + (g8>>1)*8) * 2);

    // --- prologue: Q tile (64 rows) into sKt stage 0 ---
#pragma unroll
    for (int i = 0; i < 4; i++) {
        int idx = t + i*128;
        int row = idx >> 3, seg = idx & 7;
        asm volatile("cp.async.cg.shared.global [%0], [%1], 16;"
                     :: "r"(sKtb + (uint32_t)((row*FSTRH + seg*8)*2)),
                        "l"(qp + (size_t)(qt*64 + row)*NDM + seg*8));
    }
    asm volatile("cp.async.commit_group;" ::: "memory");
    asm volatile("cp.async.wait_group 0;" ::: "memory");
    __syncthreads();

    uint32_t aq[4][4];
#pragma unroll
    for (int kq = 0; kq < 4; kq++)
        LDSM_X4(aq[kq][0], aq[kq][1], aq[kq][2], aq[kq][3],
                sKtb + qoff + (uint32_t)kq*32u);
    __syncthreads();

    // --- tile 0 (128 keys) into stage 0 ---
#pragma unroll
    for (int i = 0; i < 8; i++) {
        int idx = t + i*128;
        int row = idx >> 3, seg = idx & 7;
        asm volatile("cp.async.cg.shared.global [%0], [%1], 16;"
                     :: "r"(sKtb + (uint32_t)((row*FSTRH + seg*8)*2)),
                        "l"(kp + (size_t)row*NDM + seg*8));
        asm volatile("cp.async.cg.shared.global [%0], [%1], 16;"
                     :: "r"(sKrb + (uint32_t)((row*FSTRH + seg*8)*2)),
                        "l"(krp + (size_t)row*NDM + seg*8));
    }
    asm volatile("cp.async.commit_group;" ::: "memory");
    asm volatile("cp.async.wait_group 0;" ::: "memory");
    __syncthreads();

    float O[9][4];
#pragma unroll
    for (int q = 0; q < 9; q++) { O[q][0]=0.f; O[q][1]=0.f; O[q][2]=0.f; O[q][3]=0.f; }

    const int row0 = qt*64 + wm + gid;
    const int row1 = row0 + 8;
    const float CEXP = 0.125f * 1.4426950408889634f;
    const int nj = (qt + 2) >> 1;          // number of 128-key tiles

    for (int j = 0; j < nj; j++) {
        const int s = j & 1;
        if (j + 1 < nj) {
            const int sn = s ^ 1;
            const int kb0 = (j + 1) * 128;
#pragma unroll
            for (int i = 0; i < 8; i++) {
                int idx = t + i*128;
                int row = idx >> 3, seg = idx & 7;
                asm volatile("cp.async.cg.shared.global [%0], [%1], 16;"
                             :: "r"(sKtb + (uint32_t)(sn*KT_BYTES + (row*FSTRH + seg*8)*2)),
                                "l"(kp + (size_t)(kb0 + row)*NDM + seg*8));
                asm volatile("cp.async.cg.shared.global [%0], [%1], 16;"
                             :: "r"(sKrb + (uint32_t)(sn*KT_BYTES + (row*FSTRH + seg*8)*2)),
                                "l"(krp + (size_t)(kb0 + row)*NDM + seg*8));
            }
            asm volatile("cp.async.commit_group;" ::: "memory");
        }

        const uint32_t ktb = sKtb + (uint32_t)(s * KT_BYTES);
        const uint32_t krb = sKrb + (uint32_t)(s * KT_BYTES);
        const bool live1 = (2*j + 1) <= qt;
        const bool mask0 = (2*j == qt), mask1 = (2*j + 1 == qt);

        // ---- S0 = Q @ K[half0]^T ----
        float sc[8][4];
#pragma unroll
        for (int q = 0; q < 8; q++) { sc[q][0]=0.f; sc[q][1]=0.f; sc[q][2]=0.f; sc[q][3]=0.f; }
#pragma unroll
        for (int kq = 0; kq < 4; kq++) {
            uint32_t b[8][2];
#pragma unroll
            for (int i4 = 0; i4 < 4; i4++)
                LDSM_X4(b[2*i4][0], b[2*i4][1], b[2*i4+1][0], b[2*i4+1][1],
                        ktb + foff[i4] + (uint32_t)kq*32u);
#pragma unroll
            for (int q = 0; q < 8; q++)
                MMA_F16(sc[q][0], sc[q][1], sc[q][2], sc[q][3],
                        aq[kq][0], aq[kq][1], aq[kq][2], aq[kq][3],
                        b[q][0], b[q][1]);
        }
        if (mask0) {
            const int keybase = j*128;
#pragma unroll
            for (int q = 0; q < 8; q++) {
                int c0 = keybase + q*8 + 2*tg, c1 = c0 + 1;
                if (c0 > row0) sc[q][0] = -1e30f;
                if (c1 > row0) sc[q][1] = -1e30f;
                if (c0 > row1) sc[q][2] = -1e30f;
                if (c1 > row1) sc[q][3] = -1e30f;
            }
        }
        // ---- P0 (sc dies; its MUFU latency covered by the S1 MMAs below) ----
        uint32_t pa0[4][4];
#pragma unroll
        for (int kc = 0; kc < 4; kc++) {
            pa0[kc][0] = ex2h2(sc[2*kc  ][0]*CEXP, sc[2*kc  ][1]*CEXP);
            pa0[kc][1] = ex2h2(sc[2*kc  ][2]*CEXP, sc[2*kc  ][3]*CEXP);
            pa0[kc][2] = ex2h2(sc[2*kc+1][0]*CEXP, sc[2*kc+1][1]*CEXP);
            pa0[kc][3] = ex2h2(sc[2*kc+1][2]*CEXP, sc[2*kc+1][3]*CEXP);
        }

        // ---- S1 = Q @ K[half1]^T (independent; overlaps ex2 pipeline) ----
        if (live1) {
#pragma unroll
            for (int q = 0; q < 8; q++) { sc[q][0]=0.f; sc[q][1]=0.f; sc[q][2]=0.f; sc[q][3]=0.f; }
#pragma unroll
            for (int kq = 0; kq < 4; kq++) {
                uint32_t b[8][2];
#pragma unroll
                for (int i4 = 0; i4 < 4; i4++)
                    LDSM_X4(b[2*i4][0], b[2*i4][1], b[2*i4+1][0], b[2*i4+1][1],
                            ktb + (uint32_t)HALF_BYTES + foff[i4] + (uint32_t)kq*32u);
#pragma unroll
                for (int q = 0; q < 8; q++)
                    MMA_F16(sc[q][0], sc[q][1], sc[q][2], sc[q][3],
                            aq[kq][0], aq[kq][1], aq[kq][2], aq[kq][3],
                            b[q][0], b[q][1]);
            }
            if (mask1) {
                const int keybase = j*128 + 64;
#pragma unroll
                for (int q = 0; q < 8; q++) {
                    int c0 = keybase + q*8 + 2*tg, c1 = c0 + 1;
                    if (c0 > row0) sc[q][0] = -1e30f;
                    if (c1 > row0) sc[q][1] = -1e30f;
                    if (c0 > row1) sc[q][2] = -1e30f;
                    if (c1 > row1) sc[q][3] = -1e30f;
                }
            }
        }

        // ---- O += P0 @ [Kr half0 | ones] ----
#pragma unroll
        for (int kc = 0; kc < 4; kc++) {
            uint32_t b[8][2];
#pragma unroll
            for (int i4 = 0; i4 < 4; i4++)
                LDSM_X4_T(b[2*i4][0], b[2*i4][1], b[2*i4+1][0], b[2*i4+1][1],
                          krb + foffT[i4] + (uint32_t)(kc * 16 * FSTRH * 2));
#pragma unroll
            for (int nt = 0; nt < 8; nt++)
                MMA_F16(O[nt][0], O[nt][1], O[nt][2], O[nt][3],
                        pa0[kc][0], pa0[kc][1], pa0[kc][2], pa0[kc][3],
                        b[nt][0], b[nt][1]);
            MMA_F16(O[8][0], O[8][1], O[8][2], O[8][3],
                    pa0[kc][0], pa0[kc][1], pa0[kc][2], pa0[kc][3],
                    ONES_H2, ONES_H2);
        }

        // ---- P1 + O += P1 @ [Kr half1 | ones] ----
        if (live1) {
            uint32_t pa1[4][4];
#pragma unroll
            for (int kc = 0; kc < 4; kc++) {
                pa1[kc][0] = ex2h2(sc[2*kc  ][0]*CEXP, sc[2*kc  ][1]*CEXP);
                pa1[kc][1] = ex2h2(sc[2*kc  ][2]*CEXP, sc[2*kc  ][3]*CEXP);
                pa1[kc][2] = ex2h2(sc[2*kc+1][0]*CEXP, sc[2*kc+1][1]*CEXP);
                pa1[kc][3] = ex2h2(sc[2*kc+1][2]*CEXP, sc[2*kc+1][3]*CEXP);
            }
#pragma unroll
            for (int kc = 0; kc < 4; kc++) {
                uint32_t b[8][2];
#pragma unroll
                for (int i4 = 0; i4 < 4; i4++)
                    LDSM_X4_T(b[2*i4][0], b[2*i4][1], b[2*i4+1][0], b[2*i4+1][1],
                              krb + (uint32_t)HALF_BYTES + foffT[i4]
                                  + (uint32_t)(kc * 16 * FSTRH * 2));
#pragma unroll
                for (int nt = 0; nt < 8; nt++)
                    MMA_F16(O[nt][0], O[nt][1], O[nt][2], O[nt][3],
                            pa1[kc][0], pa1[kc][1], pa1[kc][2], pa1[kc][3],
                            b[nt][0], b[nt][1]);
                MMA_F16(O[8][0], O[8][1], O[8][2], O[8][3],
                        pa1[kc][0], pa1[kc][1], pa1[kc][2], pa1[kc][3],
                        ONES_H2, ONES_H2);
            }
        }

        if (j + 1 < nj) {
            asm volatile("cp.async.wait_group 0;" ::: "memory");
            __syncthreads();
        }
    }

    // ---- epilogue: l from ones column; Hadamard with qr; write fp16 ----
    const float inv0 = 1.f / O[8][0], inv1 = 1.f / O[8][2];
    const size_t li0 = (size_t)row0, li1 = (size_t)row1;
    __half* out0 = g_att16 + ((size_t)(bb*NL) + li0)*NDM + hh*64;
    __half* out1 = g_att16 + ((size_t)(bb*NL) + li1)*NDM + hh*64;
#pragma unroll
    for (int q = 0; q < 8; q++) {
        int d = q*8 + 2*tg;
        float2 qr0 = *(const float2*)(qrp + li0*NDM + d);
        float2 qr1 = *(const float2*)(qrp + li1*NDM + d);
        *(__half2*)(out0 + d) = __floats2half2_rn(O[q][0]*inv0*qr0.x, O[q][1]*inv0*qr0.y);
        *(__half2*)(out1 + d) = __floats2half2_rn(O[q][2]*inv1*qr1.x, O[q][3]*inv1*qr1.y);
    }
}

// ---------------------------------------------------------------------------
extern "C" void kernel_launch(void* const* d_in, const int* in_sizes, int n_in,
                              void* d_out, int out_size)
{
    const float* x   = (const float*)d_in[0];
    const float* wq  = (const float*)d_in[1];
    const float* wk  = (const float*)d_in[2];
    const float* wqr = (const float*)d_in[3];
    const float* wkr = (const float*)d_in[4];
    const float* wo  = (const float*)d_in[5];
    float* out = (float*)d_out;

    cvt_x<<<4096, 256>>>((const float4*)x);
    wcvt<<<dim3(1024, 5), 256>>>((const float4*)wq, (const float4*)wk,
                                 (const float4*)wqr, (const float4*)wkr,
                                 (const float4*)wo);

    const int gsmem = 3 * STG_HALFS * 2;   // 162816
    cudaFuncSetAttribute(gemm_tc, cudaFuncAttributeMaxDynamicSharedMemorySize, gsmem);
    gemm_tc<<<dim3(NDM/BN, NM/BM, 4), 256, gsmem>>>(out, 0);

    const int fsmem = 4 * KT_HALFS * 2;    // 73728
    cudaFuncSetAttribute(flash_mma, cudaFuncAttributeMaxDynamicSharedMemorySize, fsmem);
    flash_mma<<<dim3(NL/64, NB*NH), 128, fsmem>>>();

    gemm_tc<<<dim3(NDM/BN, NM/BM, 1), 256, gsmem>>>(out, 1);
}

// round 16
// speedup vs baseline: 1.0657x; 1.0657x over previous
#include <cuda_runtime.h>
#include <cuda_fp16.h>
#include <cstdint>

// Problem constants
#define NB 2
#define NL 2048
#define NDM 1024
#define NH 16
#define ND 64
#define NM (NB*NL)   // 4096

// Scratch — projection outputs ROW-MAJOR [m][NDM] (m = b*NL + l, col = h*64 + d)
__device__ __half g_x16[(size_t)NM*NDM];            // x rounded to fp16
__device__ __half g_w16[5][(size_t)NDM*NDM];        // weights fp16, ORIGINAL [k][n] layout
__device__ __half g_q16 [(size_t)NM*NDM];           // q
__device__ __half g_k16 [(size_t)NM*NDM];           // k
__device__ __half g_kr16[(size_t)NM*NDM];           // kr (natural; flash uses ldmatrix.trans)
__device__ float  g_qr32[(size_t)NM*NDM];           // qr fp32
__device__ __half g_att16[(size_t)NM*NDM];          // attention output fp16

// ---------------------------------------------------------------------------
__device__ __forceinline__ uint32_t smem_u32(const void* p) {
    uint32_t a;
    asm("{ .reg .u64 t; cvta.to.shared.u64 t, %1; cvt.u32.u64 %0, t; }" : "=r"(a) : "l"(p));
    return a;
}
#define MMA_F16(d0,d1,d2,d3,a0,a1,a2,a3,b0,b1) \
    asm volatile("mma.sync.aligned.m16n8k16.row.col.f32.f16.f16.f32 " \
        "{%0,%1,%2,%3},{%4,%5,%6,%7},{%8,%9},{%0,%1,%2,%3};" \
        : "+f"(d0), "+f"(d1), "+f"(d2), "+f"(d3) \
        : "r"(a0), "r"(a1), "r"(a2), "r"(a3), "r"(b0), "r"(b1))
#define LDSM_X4(r0,r1,r2,r3,addr) \
    asm volatile("ldmatrix.sync.aligned.m8n8.x4.shared.b16 {%0,%1,%2,%3}, [%4];" \
        : "=r"(r0), "=r"(r1), "=r"(r2), "=r"(r3) : "r"(addr))
#define LDSM_X4_T(r0,r1,r2,r3,addr) \
    asm volatile("ldmatrix.sync.aligned.m8n8.x4.trans.shared.b16 {%0,%1,%2,%3}, [%4];" \
        : "=r"(r0), "=r"(r1), "=r"(r2), "=r"(r3) : "r"(addr))
// exp2 of two fp32 args -> packed fp16x2
__device__ __forceinline__ uint32_t ex2h2(float a0, float a1) {
    uint32_t r;
    asm("{ .reg .b32 t; cvt.rn.f16x2.f32 t, %2, %1; ex2.approx.f16x2 %0, t; }"
        : "=r"(r) : "f"(a0), "f"(a1));
    return r;
}

// ---------------------------------------------------------------------------
// Pre-passes: elementwise fp16 conversion (no transpose anywhere)
// ---------------------------------------------------------------------------
__global__ __launch_bounds__(256) void cvt_x(const float4* __restrict__ x) {
    int i = blockIdx.x * 256 + threadIdx.x;
    float4 v = x[i];
    ((__half2*)g_x16)[2*i+0] = __floats2half2_rn(v.x, v.y);
    ((__half2*)g_x16)[2*i+1] = __floats2half2_rn(v.z, v.w);
}
__global__ __launch_bounds__(256) void wcvt(
    const float4* __restrict__ w0, const float4* __restrict__ w1,
    const float4* __restrict__ w2, const float4* __restrict__ w3,
    const float4* __restrict__ w4)
{
    int mat = blockIdx.y;
    const float4* W = (mat==0)?w0:(mat==1)?w1:(mat==2)?w2:(mat==3)?w3:w4;
    int i = blockIdx.x * 256 + threadIdx.x;      // 262144 float4 per matrix
    float4 v = W[i];
    ((__half2*)g_w16[mat])[2*i+0] = __floats2half2_rn(v.x, v.y);
    ((__half2*)g_w16[mat])[2*i+1] = __floats2half2_rn(v.z, v.w);
}

// ---------------------------------------------------------------------------
// fp16 GEMM (m16n8k16), 128x128x64 CTA tile, 128 thr / 4 warps (64x64 each),
// 3-stage cp.async with TOP-OF-ITER wait (2-iteration load lookahead).
// A [m][k] str 72h; B = W [k][n] str 136h, frags via ldmatrix.trans.
// 2 CTAs/SM. Row-major epilogue.
// mode 0: A=g_x16, W=g_w16[z] -> q/k/qr/kr. mode 1: att @ wo -> Cout.
// ---------------------------------------------------------------------------
#define BM 128
#define BN 128
#define BK 64
#define ASTRH 72                       // A row stride (halves)
#define BSTRH 136                      // B row stride (halves): trans-LDSM conflict-free
#define AHALFS (BM*ASTRH)              // 9216
#define ABYTES (AHALFS*2)              // 18432
#define BHALFS (BK*BSTRH)              // 8704
#define STG_HALFS (AHALFS + BHALFS)    // 17920 halves = 35840 B per stage
#define NITER (NDM/BK)                 // 16

__device__ __forceinline__ void load_stage(
    const __half* __restrict__ A, const __half* __restrict__ W,
    int m0, int n0, int k0, uint32_t sA, uint32_t sB, int t)
{
#pragma unroll
    for (int i = 0; i < 8; i++) {      // A tile 128x64 halves: 1024 chunks
        int idx = t + i*128;
        int row = idx >> 3, seg = idx & 7;
        asm volatile("cp.async.cg.shared.global [%0], [%1], 16;"
                     :: "r"(sA + (uint32_t)((row*ASTRH + seg*8)*2)),
                        "l"(A + (size_t)(m0 + row)*NDM + k0 + seg*8));
    }
#pragma unroll
    for (int i = 0; i < 8; i++) {      // B tile 64(k)x128(n) halves: 1024 chunks
        int idx = t + i*128;
        int row = idx >> 4, seg = idx & 15;
        asm volatile("cp.async.cg.shared.global [%0], [%1], 16;"
                     :: "r"(sB + (uint32_t)((row*BSTRH + seg*8)*2)),
                        "l"(W + (size_t)(k0 + row)*NDM + n0 + seg*8));
    }
}

__global__ __launch_bounds__(128, 2) void gemm_tc(float* __restrict__ Cout, int mode)
{
    extern __shared__ __half sm[];
    const uint32_t smb = smem_u32(sm);

    const int t = threadIdx.x;
    const int wid = t >> 5, lane = t & 31;
    const int gid = lane >> 2, tg = lane & 3;
    const int g8 = lane >> 3, lr = lane & 7;
    const int warp_m = (wid >> 1) * 64;
    const int warp_n = (wid & 1) * 64;

    const int mat = (mode == 0) ? (int)blockIdx.z : 4;
    const __half* A = (mode == 0) ? g_x16 : g_att16;
    const __half* W = g_w16[mat];
    const int m0 = blockIdx.y * BM, n0 = blockIdx.x * BN;

    uint32_t aoff[4], boffT[4];
#pragma unroll
    for (int mt = 0; mt < 4; mt++)
        aoff[mt] = (uint32_t)(((warp_m + mt*16 + (g8&1)*8 + lr)*ASTRH + (g8>>1)*8) * 2);
#pragma unroll
    for (int i = 0; i < 4; i++)   // trans pattern: row = k, col = n
        boffT[i] = (uint32_t)ABYTES +
                   (uint32_t)((((g8&1)*8 + lr)*BSTRH + warp_n + i*16 + (g8>>1)*8) * 2);

    float acc[4][8][4];
#pragma unroll
    for (int mt = 0; mt < 4; mt++)
#pragma unroll
        for (int nt = 0; nt < 8; nt++)
#pragma unroll
            for (int c = 0; c < 4; c++) acc[mt][nt][c] = 0.f;

    // prologue: commit G0, G1
#pragma unroll
    for (int p = 0; p < 2; p++) {
        uint32_t base = smb + (uint32_t)(p * STG_HALFS) * 2u;
        load_stage(A, W, m0, n0, p * BK, base, base + ABYTES, t);
        asm volatile("cp.async.commit_group;" ::: "memory");
    }

    for (int i = 0; i < NITER; i++) {
        // G_i complete (only G_{i+1} may remain pending); G_i is 2 iters old.
        asm volatile("cp.async.wait_group 1;" ::: "memory");
        __syncthreads();   // also protects stage (i+2)%3 reuse (computed iter i-1)

        if (i + 2 < NITER) {
            uint32_t base = smb + (uint32_t)(((i+2)%3) * STG_HALFS) * 2u;
            load_stage(A, W, m0, n0, (i+2)*BK, base, base + ABYTES, t);
        }
        asm volatile("cp.async.commit_group;" ::: "memory");   // G_{i+2} (maybe empty)

        const uint32_t stb = smb + (uint32_t)((i % 3) * STG_HALFS) * 2u;
#pragma unroll
        for (int kk = 0; kk < 4; kk++) {
            const uint32_t kbA = (uint32_t)kk * 32u;                 // 16 halves along k
            const uint32_t kbB = (uint32_t)(kk * 16 * BSTRH * 2);    // 16 k-rows
            uint32_t a[4][4], b[8][2];
#pragma unroll
            for (int mt = 0; mt < 4; mt++)
                LDSM_X4(a[mt][0], a[mt][1], a[mt][2], a[mt][3], stb + aoff[mt] + kbA);
#pragma unroll
            for (int i4 = 0; i4 < 4; i4++)
                LDSM_X4_T(b[2*i4][0], b[2*i4][1], b[2*i4+1][0], b[2*i4+1][1],
                          stb + boffT[i4] + kbB);
#pragma unroll
            for (int mt = 0; mt < 4; mt++)
#pragma unroll
                for (int nt = 0; nt < 8; nt++)
                    MMA_F16(acc[mt][nt][0], acc[mt][nt][1], acc[mt][nt][2], acc[mt][nt][3],
                            a[mt][0], a[mt][1], a[mt][2], a[mt][3],
                            b[nt][0], b[nt][1]);
        }
    }

    // Row-major epilogue for everything
#pragma unroll
    for (int mt = 0; mt < 4; mt++) {
#pragma unroll
        for (int nt = 0; nt < 8; nt++) {
            float v0 = acc[mt][nt][0], v1 = acc[mt][nt][1];
            float v2 = acc[mt][nt][2], v3 = acc[mt][nt][3];
            int col = n0 + warp_n + nt*8 + 2*tg;
            size_t r0 = (size_t)(m0 + warp_m + mt*16 + gid), r1 = r0 + 8;
            if (mode == 1) {
                *(float2*)(Cout + r0*NDM + col) = make_float2(v0, v1);
                *(float2*)(Cout + r1*NDM + col) = make_float2(v2, v3);
            } else if (mat == 2) {
                *(float2*)(g_qr32 + r0*NDM + col) = make_float2(v0, v1);
                *(float2*)(g_qr32 + r1*NDM + col) = make_float2(v2, v3);
            } else {
                __half* base = (mat == 0) ? g_q16 : (mat == 1) ? g_k16 : g_kr16;
                *(__half2*)(base + r0*NDM + col) = __floats2half2_rn(v0, v1);
                *(__half2*)(base + r1*NDM + col) = __floats2half2_rn(v2, v3);
            }
        }
    }
}

// ---------------------------------------------------------------------------
// Flash attention, fp16 mma, no online max. 64-query tile, 128 thr / 4 warps.
// 128-key double-buffered stages; intra-tile software pipelining:
//   S0 -> P0=ex2(S0) -> S1-mma (covers ex2 latency) -> O+=P0@Kr0 -> P1 -> O+=P1@Kr1
// Kr natural [key][d]; O-mma B frags via ldmatrix.trans.
// smem = 4 x (128*72) fp16 = 73728 B -> 3 CTAs/SM.
// ---------------------------------------------------------------------------
#define FSTRH 72
#define KT_HALFS (128*FSTRH)         // 9216 per stage
#define KT_BYTES (KT_HALFS*2)        // 18432
#define HALF_BYTES (64*FSTRH*2)      // 9216 B (64 key rows)
#define ONES_H2 0x3C003C00u

__global__ __launch_bounds__(128, 3) void flash_mma()
{
    extern __shared__ __half fh[];
    __half* sKt = fh;                          // 2 x [128][72] K natural; Q staged in stage 0
    __half* sKr = fh + 2*KT_HALFS;             // 2 x [128][72] Kr natural [key][d]
    const uint32_t sKtb = smem_u32(sKt);
    const uint32_t sKrb = smem_u32(sKr);

    const int qt = (int)(gridDim.x - 1 - blockIdx.x);   // heavy tiles first
    const int bh = blockIdx.y;
    const int bb = bh >> 4, hh = bh & 15;
    const __half* qp  = g_q16  + (size_t)(bb*NL)*NDM + hh*64;
    const __half* kp  = g_k16  + (size_t)(bb*NL)*NDM + hh*64;
    const __half* krp = g_kr16 + (size_t)(bb*NL)*NDM + hh*64;
    const float*  qrp = g_qr32 + (size_t)(bb*NL)*NDM + hh*64;

    const int t = threadIdx.x;
    const int wid = t >> 5, lane = t & 31;
    const int gid = lane >> 2, tg = lane & 3;
    const int g8 = lane >> 3, lr = lane & 7;
    const int wm = wid * 16;

    uint32_t foff[4], foffT[4];
#pragma unroll
    for (int i = 0; i < 4; i++) {
        foff[i]  = (uint32_t)(((i*16 + (g8>>1)*8 + lr)*FSTRH + (g8&1)*8) * 2);
        foffT[i] = (uint32_t)(((((g8&1)*8) + lr)*FSTRH + i*16 + (g8>>1)*8) * 2);
    }
    const uint32_t qoff =
        (uint32_t)(((wm + (g8&1)*8 + lr)*FSTRH + (g8>>1)*8) * 2);

    // --- prologue: Q tile (64 rows) into sKt stage 0 ---
#pragma unroll
    for (int i = 0; i < 4; i++) {
        int idx = t + i*128;
        int row = idx >> 3, seg = idx & 7;
        asm volatile("cp.async.cg.shared.global [%0], [%1], 16;"
                     :: "r"(sKtb + (uint32_t)((row*FSTRH + seg*8)*2)),
                        "l"(qp + (size_t)(qt*64 + row)*NDM + seg*8));
    }
    asm volatile("cp.async.commit_group;" ::: "memory");
    asm volatile("cp.async.wait_group 0;" ::: "memory");
    __syncthreads();

    uint32_t aq[4][4];
#pragma unroll
    for (int kq = 0; kq < 4; kq++)
        LDSM_X4(aq[kq][0], aq[kq][1], aq[kq][2], aq[kq][3],
                sKtb + qoff + (uint32_t)kq*32u);
    __syncthreads();

    // --- tile 0 (128 keys) into stage 0 ---
#pragma unroll
    for (int i = 0; i < 8; i++) {
        int idx = t + i*128;
        int row = idx >> 3, seg = idx & 7;
        asm volatile("cp.async.cg.shared.global [%0], [%1], 16;"
                     :: "r"(sKtb + (uint32_t)((row*FSTRH + seg*8)*2)),
                        "l"(kp + (size_t)row*NDM + seg*8));
        asm volatile("cp.async.cg.shared.global [%0], [%1], 16;"
                     :: "r"(sKrb + (uint32_t)((row*FSTRH + seg*8)*2)),
                        "l"(krp + (size_t)row*NDM + seg*8));
    }
    asm volatile("cp.async.commit_group;" ::: "memory");
    asm volatile("cp.async.wait_group 0;" ::: "memory");
    __syncthreads();

    float O[9][4];
#pragma unroll
    for (int q = 0; q < 9; q++) { O[q][0]=0.f; O[q][1]=0.f; O[q][2]=0.f; O[q][3]=0.f; }

    const int row0 = qt*64 + wm + gid;
    const int row1 = row0 + 8;
    const float CEXP = 0.125f * 1.4426950408889634f;
    const int nj = (qt + 2) >> 1;          // number of 128-key tiles

    for (int j = 0; j < nj; j++) {
        const int s = j & 1;
        if (j + 1 < nj) {
            const int sn = s ^ 1;
            const int kb0 = (j + 1) * 128;
#pragma unroll
            for (int i = 0; i < 8; i++) {
                int idx = t + i*128;
                int row = idx >> 3, seg = idx & 7;
                asm volatile("cp.async.cg.shared.global [%0], [%1], 16;"
                             :: "r"(sKtb + (uint32_t)(sn*KT_BYTES + (row*FSTRH + seg*8)*2)),
                                "l"(kp + (size_t)(kb0 + row)*NDM + seg*8));
                asm volatile("cp.async.cg.shared.global [%0], [%1], 16;"
                             :: "r"(sKrb + (uint32_t)(sn*KT_BYTES + (row*FSTRH + seg*8)*2)),
                                "l"(krp + (size_t)(kb0 + row)*NDM + seg*8));
            }
            asm volatile("cp.async.commit_group;" ::: "memory");
        }

        const uint32_t ktb = sKtb + (uint32_t)(s * KT_BYTES);
        const uint32_t krb = sKrb + (uint32_t)(s * KT_BYTES);
        const bool live1 = (2*j + 1) <= qt;
        const bool mask0 = (2*j == qt), mask1 = (2*j + 1 == qt);

        // ---- S0 = Q @ K[half0]^T ----
        float sc[8][4];
#pragma unroll
        for (int q = 0; q < 8; q++) { sc[q][0]=0.f; sc[q][1]=0.f; sc[q][2]=0.f; sc[q][3]=0.f; }
#pragma unroll
        for (int kq = 0; kq < 4; kq++) {
            uint32_t b[8][2];
#pragma unroll
            for (int i4 = 0; i4 < 4; i4++)
                LDSM_X4(b[2*i4][0], b[2*i4][1], b[2*i4+1][0], b[2*i4+1][1],
                        ktb + foff[i4] + (uint32_t)kq*32u);
#pragma unroll
            for (int q = 0; q < 8; q++)
                MMA_F16(sc[q][0], sc[q][1], sc[q][2], sc[q][3],
                        aq[kq][0], aq[kq][1], aq[kq][2], aq[kq][3],
                        b[q][0], b[q][1]);
        }
        if (mask0) {
            const int keybase = j*128;
#pragma unroll
            for (int q = 0; q < 8; q++) {
                int c0 = keybase + q*8 + 2*tg, c1 = c0 + 1;
                if (c0 > row0) sc[q][0] = -1e30f;
                if (c1 > row0) sc[q][1] = -1e30f;
                if (c0 > row1) sc[q][2] = -1e30f;
                if (c1 > row1) sc[q][3] = -1e30f;
            }
        }
        // ---- P0 (sc dies; its MUFU latency covered by the S1 MMAs below) ----
        uint32_t pa0[4][4];
#pragma unroll
        for (int kc = 0; kc < 4; kc++) {
            pa0[kc][0] = ex2h2(sc[2*kc  ][0]*CEXP, sc[2*kc  ][1]*CEXP);
            pa0[kc][1] = ex2h2(sc[2*kc  ][2]*CEXP, sc[2*kc  ][3]*CEXP);
            pa0[kc][2] = ex2h2(sc[2*kc+1][0]*CEXP, sc[2*kc+1][1]*CEXP);
            pa0[kc][3] = ex2h2(sc[2*kc+1][2]*CEXP, sc[2*kc+1][3]*CEXP);
        }

        // ---- S1 = Q @ K[half1]^T (independent; overlaps ex2 pipeline) ----
        if (live1) {
#pragma unroll
            for (int q = 0; q < 8; q++) { sc[q][0]=0.f; sc[q][1]=0.f; sc[q][2]=0.f; sc[q][3]=0.f; }
#pragma unroll
            for (int kq = 0; kq < 4; kq++) {
                uint32_t b[8][2];
#pragma unroll
                for (int i4 = 0; i4 < 4; i4++)
                    LDSM_X4(b[2*i4][0], b[2*i4][1], b[2*i4+1][0], b[2*i4+1][1],
                            ktb + (uint32_t)HALF_BYTES + foff[i4] + (uint32_t)kq*32u);
#pragma unroll
                for (int q = 0; q < 8; q++)
                    MMA_F16(sc[q][0], sc[q][1], sc[q][2], sc[q][3],
                            aq[kq][0], aq[kq][1], aq[kq][2], aq[kq][3],
                            b[q][0], b[q][1]);
            }
            if (mask1) {
                const int keybase = j*128 + 64;
#pragma unroll
                for (int q = 0; q < 8; q++) {
                    int c0 = keybase + q*8 + 2*tg, c1 = c0 + 1;
                    if (c0 > row0) sc[q][0] = -1e30f;
                    if (c1 > row0) sc[q][1] = -1e30f;
                    if (c0 > row1) sc[q][2] = -1e30f;
                    if (c1 > row1) sc[q][3] = -1e30f;
                }
            }
        }

        // ---- O += P0 @ [Kr half0 | ones] ----
#pragma unroll
        for (int kc = 0; kc < 4; kc++) {
            uint32_t b[8][2];
#pragma unroll
            for (int i4 = 0; i4 < 4; i4++)
                LDSM_X4_T(b[2*i4][0], b[2*i4][1], b[2*i4+1][0], b[2*i4+1][1],
                          krb + foffT[i4] + (uint32_t)(kc * 16 * FSTRH * 2));
#pragma unroll
            for (int nt = 0; nt < 8; nt++)
                MMA_F16(O[nt][0], O[nt][1], O[nt][2], O[nt][3],
                        pa0[kc][0], pa0[kc][1], pa0[kc][2], pa0[kc][3],
                        b[nt][0], b[nt][1]);
            MMA_F16(O[8][0], O[8][1], O[8][2], O[8][3],
                    pa0[kc][0], pa0[kc][1], pa0[kc][2], pa0[kc][3],
                    ONES_H2, ONES_H2);
        }

        // ---- P1 + O += P1 @ [Kr half1 | ones] ----
        if (live1) {
            uint32_t pa1[4][4];
#pragma unroll
            for (int kc = 0; kc < 4; kc++) {
                pa1[kc][0] = ex2h2(sc[2*kc  ][0]*CEXP, sc[2*kc  ][1]*CEXP);
                pa1[kc][1] = ex2h2(sc[2*kc  ][2]*CEXP, sc[2*kc  ][3]*CEXP);
                pa1[kc][2] = ex2h2(sc[2*kc+1][0]*CEXP, sc[2*kc+1][1]*CEXP);
                pa1[kc][3] = ex2h2(sc[2*kc+1][2]*CEXP, sc[2*kc+1][3]*CEXP);
            }
#pragma unroll
            for (int kc = 0; kc < 4; kc++) {
                uint32_t b[8][2];
#pragma unroll
                for (int i4 = 0; i4 < 4; i4++)
                    LDSM_X4_T(b[2*i4][0], b[2*i4][1], b[2*i4+1][0], b[2*i4+1][1],
                              krb + (uint32_t)HALF_BYTES + foffT[i4]
                                  + (uint32_t)(kc * 16 * FSTRH * 2));
#pragma unroll
                for (int nt = 0; nt < 8; nt++)
                    MMA_F16(O[nt][0], O[nt][1], O[nt][2], O[nt][3],
                            pa1[kc][0], pa1[kc][1], pa1[kc][2], pa1[kc][3],
                            b[nt][0], b[nt][1]);
                MMA_F16(O[8][0], O[8][1], O[8][2], O[8][3],
                        pa1[kc][0], pa1[kc][1], pa1[kc][2], pa1[kc][3],
                        ONES_H2, ONES_H2);
            }
        }

        if (j + 1 < nj) {
            asm volatile("cp.async.wait_group 0;" ::: "memory");
            __syncthreads();
        }
    }

    // ---- epilogue: l from ones column; Hadamard with qr; write fp16 ----
    const float inv0 = 1.f / O[8][0], inv1 = 1.f / O[8][2];
    const size_t li0 = (size_t)row0, li1 = (size_t)row1;
    __half* out0 = g_att16 + ((size_t)(bb*NL) + li0)*NDM + hh*64;
    __half* out1 = g_att16 + ((size_t)(bb*NL) + li1)*NDM + hh*64;
#pragma unroll
    for (int q = 0; q < 8; q++) {
        int d = q*8 + 2*tg;
        float2 qr0 = *(const float2*)(qrp + li0*NDM + d);
        float2 qr1 = *(const float2*)(qrp + li1*NDM + d);
        *(__half2*)(out0 + d) = __floats2half2_rn(O[q][0]*inv0*qr0.x, O[q][1]*inv0*qr0.y);
        *(__half2*)(out1 + d) = __floats2half2_rn(O[q][2]*inv1*qr1.x, O[q][3]*inv1*qr1.y);
    }
}

// ---------------------------------------------------------------------------
extern "C" void kernel_launch(void* const* d_in, const int* in_sizes, int n_in,
                              void* d_out, int out_size)
{
    const float* x   = (const float*)d_in[0];
    const float* wq  = (const float*)d_in[1];
    const float* wk  = (const float*)d_in[2];
    const float* wqr = (const float*)d_in[3];
    const float* wkr = (const float*)d_in[4];
    const float* wo  = (const float*)d_in[5];
    float* out = (float*)d_out;

    cvt_x<<<4096, 256>>>((const float4*)x);
    wcvt<<<dim3(1024, 5), 256>>>((const float4*)wq, (const float4*)wk,
                                 (const float4*)wqr, (const float4*)wkr,
                                 (const float4*)wo);

    const int gsmem = 3 * STG_HALFS * 2;   // 107520
    cudaFuncSetAttribute(gemm_tc, cudaFuncAttributeMaxDynamicSharedMemorySize, gsmem);
    gemm_tc<<<dim3(NDM/BN, NM/BM, 4), 128, gsmem>>>(out, 0);

    const int fsmem = 4 * KT_HALFS * 2;    // 73728
    cudaFuncSetAttribute(flash_mma, cudaFuncAttributeMaxDynamicSharedMemorySize, fsmem);
    flash_mma<<<dim3(NL/64, NB*NH), 128, fsmem>>>();

    gemm_tc<<<dim3(NDM/BN, NM/BM, 1), 128, gsmem>>>(out, 1);
}

// round 17
// speedup vs baseline: 1.1282x; 1.0586x over previous
#include <cuda_runtime.h>
#include <cuda_fp16.h>
#include <cstdint>

// Problem constants
#define NB 2
#define NL 2048
#define NDM 1024
#define NH 16
#define ND 64
#define NM (NB*NL)   // 4096

// Scratch — projection outputs ROW-MAJOR [m][NDM] (m = b*NL + l, col = h*64 + d)
__device__ __half g_x16[(size_t)NM*NDM];            // x rounded to fp16
__device__ __half g_wt16[5][(size_t)NDM*NDM];       // transposed weights [n][k] fp16
__device__ __half g_q16 [(size_t)NM*NDM];           // q
__device__ __half g_k16 [(size_t)NM*NDM];           // k
__device__ __half g_kr16[(size_t)NM*NDM];           // kr (natural; flash uses ldmatrix.trans)
__device__ float  g_qr32[(size_t)NM*NDM];           // qr fp32
__device__ __half g_att16[(size_t)NM*NDM];          // attention output fp16

// ---------------------------------------------------------------------------
__device__ __forceinline__ uint32_t smem_u32(const void* p) {
    uint32_t a;
    asm("{ .reg .u64 t; cvta.to.shared.u64 t, %1; cvt.u32.u64 %0, t; }" : "=r"(a) : "l"(p));
    return a;
}
#define MMA_F16(d0,d1,d2,d3,a0,a1,a2,a3,b0,b1) \
    asm volatile("mma.sync.aligned.m16n8k16.row.col.f32.f16.f16.f32 " \
        "{%0,%1,%2,%3},{%4,%5,%6,%7},{%8,%9},{%0,%1,%2,%3};" \
        : "+f"(d0), "+f"(d1), "+f"(d2), "+f"(d3) \
        : "r"(a0), "r"(a1), "r"(a2), "r"(a3), "r"(b0), "r"(b1))
#define LDSM_X4(r0,r1,r2,r3,addr) \
    asm volatile("ldmatrix.sync.aligned.m8n8.x4.shared.b16 {%0,%1,%2,%3}, [%4];" \
        : "=r"(r0), "=r"(r1), "=r"(r2), "=r"(r3) : "r"(addr))
#define LDSM_X4_T(r0,r1,r2,r3,addr) \
    asm volatile("ldmatrix.sync.aligned.m8n8.x4.trans.shared.b16 {%0,%1,%2,%3}, [%4];" \
        : "=r"(r0), "=r"(r1), "=r"(r2), "=r"(r3) : "r"(addr))
// exp2 of two fp32 args -> packed fp16x2
__device__ __forceinline__ uint32_t ex2h2(float a0, float a1) {
    uint32_t r;
    asm("{ .reg .b32 t; cvt.rn.f16x2.f32 t, %2, %1; ex2.approx.f16x2 %0, t; }"
        : "=r"(r) : "f"(a0), "f"(a1));
    return r;
}

// ---------------------------------------------------------------------------
// Pre-passes: x -> fp16; weights -> transposed fp16 [n][k]
// ---------------------------------------------------------------------------
__global__ __launch_bounds__(256) void cvt_x(const float4* __restrict__ x) {
    int i = blockIdx.x * 256 + threadIdx.x;
    float4 v = x[i];
    ((__half2*)g_x16)[2*i+0] = __floats2half2_rn(v.x, v.y);
    ((__half2*)g_x16)[2*i+1] = __floats2half2_rn(v.z, v.w);
}
__global__ __launch_bounds__(256) void wtrans(
    const float* __restrict__ w0, const float* __restrict__ w1,
    const float* __restrict__ w2, const float* __restrict__ w3,
    const float* __restrict__ w4)
{
    __shared__ float tl[32][33];
    const float* W = (blockIdx.z==0)?w0:(blockIdx.z==1)?w1:(blockIdx.z==2)?w2:(blockIdx.z==3)?w3:w4;
    __half* Wt = g_wt16[blockIdx.z];
    int n0 = blockIdx.x * 32, k0 = blockIdx.y * 32;
    int tx = threadIdx.x & 31, ty = threadIdx.x >> 5;
#pragma unroll
    for (int j = 0; j < 4; j++)
        tl[ty + j*8][tx] = W[(size_t)(k0 + ty + j*8)*NDM + n0 + tx];
    __syncthreads();
#pragma unroll
    for (int j = 0; j < 4; j++)
        Wt[(size_t)(n0 + ty + j*8)*NDM + k0 + tx] = __float2half(tl[tx][ty + j*8]);
}

// ---------------------------------------------------------------------------
// fp16 GEMM (m16n8k16), 128x128x64 CTA tile, 128 thr / 4 warps (64x64 each),
// 3-stage cp.async, bottom-of-loop wait (R12 schedule — best measured).
// A [m][k] str 72h; B = W^T [n][k] str 72h; both frags via non-trans ldmatrix.
// 2 CTAs/SM. Row-major epilogue for all outputs.
// mode 0: A=g_x16, W=g_wt16[z] -> q/k/qr/kr. mode 1: att @ wo -> Cout.
// ---------------------------------------------------------------------------
#define BM 128
#define BN 128
#define BK 64
#define ASTRH 72
#define AHALFS (BM*ASTRH)              // 9216
#define ABYTES (AHALFS*2)              // 18432
#define STG_HALFS (2*AHALFS)           // 18432 halves = 36864 B per stage
#define NITER (NDM/BK)                 // 16

__device__ __forceinline__ void load_stage(
    const __half* __restrict__ A, const __half* __restrict__ Wt,
    int m0, int n0, int k0, uint32_t sA, uint32_t sB, int t)
{
#pragma unroll
    for (int i = 0; i < 8; i++) {      // A tile 128x64 halves: 1024 chunks
        int idx = t + i*128;
        int row = idx >> 3, seg = idx & 7;
        asm volatile("cp.async.cg.shared.global [%0], [%1], 16;"
                     :: "r"(sA + (uint32_t)((row*ASTRH + seg*8)*2)),
                        "l"(A + (size_t)(m0 + row)*NDM + k0 + seg*8));
    }
#pragma unroll
    for (int i = 0; i < 8; i++) {      // B tile 128(n)x64(k) halves
        int idx = t + i*128;
        int row = idx >> 3, seg = idx & 7;
        asm volatile("cp.async.cg.shared.global [%0], [%1], 16;"
                     :: "r"(sB + (uint32_t)((row*ASTRH + seg*8)*2)),
                        "l"(Wt + (size_t)(n0 + row)*NDM + k0 + seg*8));
    }
}

__global__ __launch_bounds__(128, 2) void gemm_tc(float* __restrict__ Cout, int mode)
{
    extern __shared__ __half sm[];
    const uint32_t smb = smem_u32(sm);

    const int t = threadIdx.x;
    const int wid = t >> 5, lane = t & 31;
    const int gid = lane >> 2, tg = lane & 3;
    const int g8 = lane >> 3, lr = lane & 7;
    const int warp_m = (wid >> 1) * 64;
    const int warp_n = (wid & 1) * 64;

    const int mat = (mode == 0) ? (int)blockIdx.z : 4;
    const __half* A = (mode == 0) ? g_x16 : g_att16;
    const __half* W = g_wt16[mat];
    const int m0 = blockIdx.y * BM, n0 = blockIdx.x * BN;

    uint32_t aoff[4], boff[4];
#pragma unroll
    for (int mt = 0; mt < 4; mt++)
        aoff[mt] = (uint32_t)(((warp_m + mt*16 + (g8&1)*8 + lr)*ASTRH + (g8>>1)*8) * 2);
#pragma unroll
    for (int i = 0; i < 4; i++)
        boff[i] = (uint32_t)ABYTES +
                  (uint32_t)(((warp_n + i*16 + (g8>>1)*8 + lr)*ASTRH + (g8&1)*8) * 2);

    float acc[4][8][4];
#pragma unroll
    for (int mt = 0; mt < 4; mt++)
#pragma unroll
        for (int nt = 0; nt < 8; nt++)
#pragma unroll
            for (int c = 0; c < 4; c++) acc[mt][nt][c] = 0.f;

#pragma unroll
    for (int p = 0; p < 2; p++) {
        uint32_t base = smb + (uint32_t)(p * STG_HALFS) * 2u;
        load_stage(A, W, m0, n0, p * BK, base, base + ABYTES, t);
        asm volatile("cp.async.commit_group;" ::: "memory");
    }
    asm volatile("cp.async.wait_group 1;" ::: "memory");
    __syncthreads();

    for (int i = 0; i < NITER; i++) {
        const int s = i % 3;
        if (i + 2 < NITER) {
            uint32_t base = smb + (uint32_t)(((i+2)%3) * STG_HALFS) * 2u;
            load_stage(A, W, m0, n0, (i+2)*BK, base, base + ABYTES, t);
        }
        asm volatile("cp.async.commit_group;" ::: "memory");

        const uint32_t stb = smb + (uint32_t)(s * STG_HALFS) * 2u;
#pragma unroll
        for (int kk = 0; kk < 4; kk++) {
            const uint32_t kb = (uint32_t)kk * 32u;    // 16 halves along k
            uint32_t a[4][4], b[8][2];
#pragma unroll
            for (int mt = 0; mt < 4; mt++)
                LDSM_X4(a[mt][0], a[mt][1], a[mt][2], a[mt][3], stb + aoff[mt] + kb);
#pragma unroll
            for (int i4 = 0; i4 < 4; i4++)
                LDSM_X4(b[2*i4][0], b[2*i4][1], b[2*i4+1][0], b[2*i4+1][1],
                        stb + boff[i4] + kb);
#pragma unroll
            for (int mt = 0; mt < 4; mt++)
#pragma unroll
                for (int nt = 0; nt < 8; nt++)
                    MMA_F16(acc[mt][nt][0], acc[mt][nt][1], acc[mt][nt][2], acc[mt][nt][3],
                            a[mt][0], a[mt][1], a[mt][2], a[mt][3],
                            b[nt][0], b[nt][1]);
        }

        asm volatile("cp.async.wait_group 1;" ::: "memory");
        __syncthreads();
    }

    // Row-major epilogue for everything
#pragma unroll
    for (int mt = 0; mt < 4; mt++) {
#pragma unroll
        for (int nt = 0; nt < 8; nt++) {
            float v0 = acc[mt][nt][0], v1 = acc[mt][nt][1];
            float v2 = acc[mt][nt][2], v3 = acc[mt][nt][3];
            int col = n0 + warp_n + nt*8 + 2*tg;
            size_t r0 = (size_t)(m0 + warp_m + mt*16 + gid), r1 = r0 + 8;
            if (mode == 1) {
                *(float2*)(Cout + r0*NDM + col) = make_float2(v0, v1);
                *(float2*)(Cout + r1*NDM + col) = make_float2(v2, v3);
            } else if (mat == 2) {
                *(float2*)(g_qr32 + r0*NDM + col) = make_float2(v0, v1);
                *(float2*)(g_qr32 + r1*NDM + col) = make_float2(v2, v3);
            } else {
                __half* base = (mat == 0) ? g_q16 : (mat == 1) ? g_k16 : g_kr16;
                *(__half2*)(base + r0*NDM + col) = __floats2half2_rn(v0, v1);
                *(__half2*)(base + r1*NDM + col) = __floats2half2_rn(v2, v3);
            }
        }
    }
}

// ---------------------------------------------------------------------------
// Flash attention (R14 config — best measured), fp16 mma, no online max.
// 64-query tile, 128 thr / 4 warps. 128-key double-buffered stages;
// intra-tile pipelining: S0 -> P0 -> S1-mma -> O+=P0@Kr0 -> P1 -> O+=P1@Kr1.
// Kr natural [key][d]; O-mma B frags via ldmatrix.trans.
// smem = 4 x (128*72) fp16 = 73728 B -> 3 CTAs/SM.
// ---------------------------------------------------------------------------
#define FSTRH 72
#define KT_HALFS (128*FSTRH)         // 9216 per stage
#define KT_BYTES (KT_HALFS*2)        // 18432
#define HALF_BYTES (64*FSTRH*2)      // 9216 B (64 key rows)
#define ONES_H2 0x3C003C00u

__global__ __launch_bounds__(128, 3) void flash_mma()
{
    extern __shared__ __half fh[];
    __half* sKt = fh;                          // 2 x [128][72] K natural; Q staged in stage 0
    __half* sKr = fh + 2*KT_HALFS;             // 2 x [128][72] Kr natural [key][d]
    const uint32_t sKtb = smem_u32(sKt);
    const uint32_t sKrb = smem_u32(sKr);

    const int qt = (int)(gridDim.x - 1 - blockIdx.x);   // heavy tiles first
    const int bh = blockIdx.y;
    const int bb = bh >> 4, hh = bh & 15;
    const __half* qp  = g_q16  + (size_t)(bb*NL)*NDM + hh*64;
    const __half* kp  = g_k16  + (size_t)(bb*NL)*NDM + hh*64;
    const __half* krp = g_kr16 + (size_t)(bb*NL)*NDM + hh*64;
    const float*  qrp = g_qr32 + (size_t)(bb*NL)*NDM + hh*64;

    const int t = threadIdx.x;
    const int wid = t >> 5, lane = t & 31;
    const int gid = lane >> 2, tg = lane & 3;
    const int g8 = lane >> 3, lr = lane & 7;
    const int wm = wid * 16;

    uint32_t foff[4], foffT[4];
#pragma unroll
    for (int i = 0; i < 4; i++) {
        foff[i]  = (uint32_t)(((i*16 + (g8>>1)*8 + lr)*FSTRH + (g8&1)*8) * 2);
        foffT[i] = (uint32_t)(((((g8&1)*8) + lr)*FSTRH + i*16 + (g8>>1)*8) * 2);
    }
    const uint32_t qoff =
        (uint32_t)(((wm + (g8&1)*8 + lr)*FSTRH + (g8>>1)*8) * 2);

    // --- prologue: Q tile (64 rows) into sKt stage 0 ---
#pragma unroll
    for (int i = 0; i < 4; i++) {
        int idx = t + i*128;
        int row = idx >> 3, seg = idx & 7;
        asm volatile("cp.async.cg.shared.global [%0], [%1], 16;"
                     :: "r"(sKtb + (uint32_t)((row*FSTRH + seg*8)*2)),
                        "l"(qp + (size_t)(qt*64 + row)*NDM + seg*8));
    }
    asm volatile("cp.async.commit_group;" ::: "memory");
    asm volatile("cp.async.wait_group 0;" ::: "memory");
    __syncthreads();

    uint32_t aq[4][4];
#pragma unroll
    for (int kq = 0; kq < 4; kq++)
        LDSM_X4(aq[kq][0], aq[kq][1], aq[kq][2], aq[kq][3],
                sKtb + qoff + (uint32_t)kq*32u);
    __syncthreads();

    // --- tile 0 (128 keys) into stage 0 ---
#pragma unroll
    for (int i = 0; i < 8; i++) {
        int idx = t + i*128;
        int row = idx >> 3, seg = idx & 7;
        asm volatile("cp.async.cg.shared.global [%0], [%1], 16;"
                     :: "r"(sKtb + (uint32_t)((row*FSTRH + seg*8)*2)),
                        "l"(kp + (size_t)row*NDM + seg*8));
        asm volatile("cp.async.cg.shared.global [%0], [%1], 16;"
                     :: "r"(sKrb + (uint32_t)((row*FSTRH + seg*8)*2)),
                        "l"(krp + (size_t)row*NDM + seg*8));
    }
    asm volatile("cp.async.commit_group;" ::: "memory");
    asm volatile("cp.async.wait_group 0;" ::: "memory");
    __syncthreads();

    float O[9][4];
#pragma unroll
    for (int q = 0; q < 9; q++) { O[q][0]=0.f; O[q][1]=0.f; O[q][2]=0.f; O[q][3]=0.f; }

    const int row0 = qt*64 + wm + gid;
    const int row1 = row0 + 8;
    const float CEXP = 0.125f * 1.4426950408889634f;
    const int nj = (qt + 2) >> 1;

    for (int j = 0; j < nj; j++) {
        const int s = j & 1;
        if (j + 1 < nj) {
            const int sn = s ^ 1;
            const int kb0 = (j + 1) * 128;
#pragma unroll
            for (int i = 0; i < 8; i++) {
                int idx = t + i*128;
                int row = idx >> 3, seg = idx & 7;
                asm volatile("cp.async.cg.shared.global [%0], [%1], 16;"
                             :: "r"(sKtb + (uint32_t)(sn*KT_BYTES + (row*FSTRH + seg*8)*2)),
                                "l"(kp + (size_t)(kb0 + row)*NDM + seg*8));
                asm volatile("cp.async.cg.shared.global [%0], [%1], 16;"
                             :: "r"(sKrb + (uint32_t)(sn*KT_BYTES + (row*FSTRH + seg*8)*2)),
                                "l"(krp + (size_t)(kb0 + row)*NDM + seg*8));
            }
            asm volatile("cp.async.commit_group;" ::: "memory");
        }

        const uint32_t ktb = sKtb + (uint32_t)(s * KT_BYTES);
        const uint32_t krb = sKrb + (uint32_t)(s * KT_BYTES);
        const bool live1 = (2*j + 1) <= qt;
        const bool mask0 = (2*j == qt), mask1 = (2*j + 1 == qt);

        // ---- S0 = Q @ K[half0]^T ----
        float sc[8][4];
#pragma unroll
        for (int q = 0; q < 8; q++) { sc[q][0]=0.f; sc[q][1]=0.f; sc[q][2]=0.f; sc[q][3]=0.f; }
#pragma unroll
        for (int kq = 0; kq < 4; kq++) {
            uint32_t b[8][2];
#pragma unroll
            for (int i4 = 0; i4 < 4; i4++)
                LDSM_X4(b[2*i4][0], b[2*i4][1], b[2*i4+1][0], b[2*i4+1][1],
                        ktb + foff[i4] + (uint32_t)kq*32u);
#pragma unroll
            for (int q = 0; q < 8; q++)
                MMA_F16(sc[q][0], sc[q][1], sc[q][2], sc[q][3],
                        aq[kq][0], aq[kq][1], aq[kq][2], aq[kq][3],
                        b[q][0], b[q][1]);
        }
        if (mask0) {
            const int keybase = j*128;
#pragma unroll
            for (int q = 0; q < 8; q++) {
                int c0 = keybase + q*8 + 2*tg, c1 = c0 + 1;
                if (c0 > row0) sc[q][0] = -1e30f;
                if (c1 > row0) sc[q][1] = -1e30f;
                if (c0 > row1) sc[q][2] = -1e30f;
                if (c1 > row1) sc[q][3] = -1e30f;
            }
        }
        // ---- P0 (ex2 latency covered by S1 MMAs below) ----
        uint32_t pa0[4][4];
#pragma unroll
        for (int kc = 0; kc < 4; kc++) {
            pa0[kc][0] = ex2h2(sc[2*kc  ][0]*CEXP, sc[2*kc  ][1]*CEXP);
            pa0[kc][1] = ex2h2(sc[2*kc  ][2]*CEXP, sc[2*kc  ][3]*CEXP);
            pa0[kc][2] = ex2h2(sc[2*kc+1][0]*CEXP, sc[2*kc+1][1]*CEXP);
            pa0[kc][3] = ex2h2(sc[2*kc+1][2]*CEXP, sc[2*kc+1][3]*CEXP);
        }

        // ---- S1 = Q @ K[half1]^T ----
        if (live1) {
#pragma unroll
            for (int q = 0; q < 8; q++) { sc[q][0]=0.f; sc[q][1]=0.f; sc[q][2]=0.f; sc[q][3]=0.f; }
#pragma unroll
            for (int kq = 0; kq < 4; kq++) {
                uint32_t b[8][2];
#pragma unroll
                for (int i4 = 0; i4 < 4; i4++)
                    LDSM_X4(b[2*i4][0], b[2*i4][1], b[2*i4+1][0], b[2*i4+1][1],
                            ktb + (uint32_t)HALF_BYTES + foff[i4] + (uint32_t)kq*32u);
#pragma unroll
                for (int q = 0; q < 8; q++)
                    MMA_F16(sc[q][0], sc[q][1], sc[q][2], sc[q][3],
                            aq[kq][0], aq[kq][1], aq[kq][2], aq[kq][3],
                            b[q][0], b[q][1]);
            }
            if (mask1) {
                const int keybase = j*128 + 64;
#pragma unroll
                for (int q = 0; q < 8; q++) {
                    int c0 = keybase + q*8 + 2*tg, c1 = c0 + 1;
                    if (c0 > row0) sc[q][0] = -1e30f;
                    if (c1 > row0) sc[q][1] = -1e30f;
                    if (c0 > row1) sc[q][2] = -1e30f;
                    if (c1 > row1) sc[q][3] = -1e30f;
                }
            }
        }

        // ---- O += P0 @ [Kr half0 | ones] ----
#pragma unroll
        for (int kc = 0; kc < 4; kc++) {
            uint32_t b[8][2];
#pragma unroll
            for (int i4 = 0; i4 < 4; i4++)
                LDSM_X4_T(b[2*i4][0], b[2*i4][1], b[2*i4+1][0], b[2*i4+1][1],
                          krb + foffT[i4] + (uint32_t)(kc * 16 * FSTRH * 2));
#pragma unroll
            for (int nt = 0; nt < 8; nt++)
                MMA_F16(O[nt][0], O[nt][1], O[nt][2], O[nt][3],
                        pa0[kc][0], pa0[kc][1], pa0[kc][2], pa0[kc][3],
                        b[nt][0], b[nt][1]);
            MMA_F16(O[8][0], O[8][1], O[8][2], O[8][3],
                    pa0[kc][0], pa0[kc][1], pa0[kc][2], pa0[kc][3],
                    ONES_H2, ONES_H2);
        }

        // ---- P1 + O += P1 @ [Kr half1 | ones] ----
        if (live1) {
            uint32_t pa1[4][4];
#pragma unroll
            for (int kc = 0; kc < 4; kc++) {
                pa1[kc][0] = ex2h2(sc[2*kc  ][0]*CEXP, sc[2*kc  ][1]*CEXP);
                pa1[kc][1] = ex2h2(sc[2*kc  ][2]*CEXP, sc[2*kc  ][3]*CEXP);
                pa1[kc][2] = ex2h2(sc[2*kc+1][0]*CEXP, sc[2*kc+1][1]*CEXP);
                pa1[kc][3] = ex2h2(sc[2*kc+1][2]*CEXP, sc[2*kc+1][3]*CEXP);
            }
#pragma unroll
            for (int kc = 0; kc < 4; kc++) {
                uint32_t b[8][2];
#pragma unroll
                for (int i4 = 0; i4 < 4; i4++)
                    LDSM_X4_T(b[2*i4][0], b[2*i4][1], b[2*i4+1][0], b[2*i4+1][1],
                              krb + (uint32_t)HALF_BYTES + foffT[i4]
                                  + (uint32_t)(kc * 16 * FSTRH * 2));
#pragma unroll
                for (int nt = 0; nt < 8; nt++)
                    MMA_F16(O[nt][0], O[nt][1], O[nt][2], O[nt][3],
                            pa1[kc][0], pa1[kc][1], pa1[kc][2], pa1[kc][3],
                            b[nt][0], b[nt][1]);
                MMA_F16(O[8][0], O[8][1], O[8][2], O[8][3],
                        pa1[kc][0], pa1[kc][1], pa1[kc][2], pa1[kc][3],
                        ONES_H2, ONES_H2);
            }
        }

        if (j + 1 < nj) {
            asm volatile("cp.async.wait_group 0;" ::: "memory");
            __syncthreads();
        }
    }

    // ---- epilogue: l from ones column; Hadamard with qr; write fp16 ----
    const float inv0 = 1.f / O[8][0], inv1 = 1.f / O[8][2];
    const size_t li0 = (size_t)row0, li1 = (size_t)row1;
    __half* out0 = g_att16 + ((size_t)(bb*NL) + li0)*NDM + hh*64;
    __half* out1 = g_att16 + ((size_t)(bb*NL) + li1)*NDM + hh*64;
#pragma unroll
    for (int q = 0; q < 8; q++) {
        int d = q*8 + 2*tg;
        float2 qr0 = *(const float2*)(qrp + li0*NDM + d);
        float2 qr1 = *(const float2*)(qrp + li1*NDM + d);
        *(__half2*)(out0 + d) = __floats2half2_rn(O[q][0]*inv0*qr0.x, O[q][1]*inv0*qr0.y);
        *(__half2*)(out1 + d) = __floats2half2_rn(O[q][2]*inv1*qr1.x, O[q][3]*inv1*qr1.y);
    }
}

// ---------------------------------------------------------------------------
extern "C" void kernel_launch(void* const* d_in, const int* in_sizes, int n_in,
                              void* d_out, int out_size)
{
    const float* x   = (const float*)d_in[0];
    const float* wq  = (const float*)d_in[1];
    const float* wk  = (const float*)d_in[2];
    const float* wqr = (const float*)d_in[3];
    const float* wkr = (const float*)d_in[4];
    const float* wo  = (const float*)d_in[5];
    float* out = (float*)d_out;

    cvt_x<<<4096, 256>>>((const float4*)x);
    wtrans<<<dim3(32, 32, 5), 256>>>(wq, wk, wqr, wkr, wo);

    const int gsmem = 3 * STG_HALFS * 2;   // 110592
    cudaFuncSetAttribute(gemm_tc, cudaFuncAttributeMaxDynamicSharedMemorySize, gsmem);
    gemm_tc<<<dim3(NDM/BN, NM/BM, 4), 128, gsmem>>>(out, 0);

    const int fsmem = 4 * KT_HALFS * 2;    // 73728
    cudaFuncSetAttribute(flash_mma, cudaFuncAttributeMaxDynamicSharedMemorySize, fsmem);
    flash_mma<<<dim3(NL/64, NB*NH), 128, fsmem>>>();

    gemm_tc<<<dim3(NDM/BN, NM/BM, 1), 128, gsmem>>>(out, 1);
}